// round 14
// baseline (speedup 1.0000x reference)
#include <cuda_runtime.h>
#include <cuda_bf16.h>
#include <cuda_fp8.h>
#include <mma.h>

using namespace nvcuda;

#define NN   50000
#define EE   800000
#define FIN  256
#define HH   8
#define CC   32
#define HC   256   // HH*CC
#define NOUT 40
#define NEG_SLOPE 0.2f
#define NB   ((NN + 255) / 256)

// ---------------- device scratch ----------------
__device__ unsigned char g_h[(size_t)NN * HC];   // 12.8 MB : projected features (fp8 e4m3)
__device__ float g_act1[(size_t)NN * CC];
__device__ float g_asrc[NN * HH];
__device__ float g_adst[NN * HH];
__device__ int   g_deg[NN];
__device__ int   g_rowptr[NN + 1];
__device__ int   g_rank[EE];      // per-edge rank within its dst bucket
__device__ int   g_csr[EE];

// fp8x2 -> float2 helper
__device__ __forceinline__ float2 fp8x2_to_float2(unsigned short v) {
    __half2_raw hr = __nv_cvt_fp8x2_to_halfraw2((__nv_fp8x2_storage_t)v, __NV_E4M3);
    return __half22float2(*(__half2*)&hr);
}

// ---------------- CSR build ----------------
__global__ void count_kernel(const int* __restrict__ ei) {
    int e = blockIdx.x * blockDim.x + threadIdx.x;
    if (e < EE) g_rank[e] = atomicAdd(&g_deg[ei[EE + e]], 1);
}

// block b sums deg[0..256b) coalescedly for its offset, then local scan -> rowptr
__global__ void scan_kernel() {
    __shared__ int sm[256];
    __shared__ int swsum[8];
    int b = blockIdx.x, t = threadIdx.x;

    int pre = 0;
    int lim = b * 256;
    for (int base = t; base < lim; base += 256) pre += g_deg[base];
#pragma unroll
    for (int o = 16; o > 0; o >>= 1) pre += __shfl_xor_sync(0xffffffffu, pre, o);
    if ((t & 31) == 0) swsum[t >> 5] = pre;
    __syncthreads();
    int boff = 0;
#pragma unroll
    for (int k = 0; k < 8; k++) boff += swsum[k];

    int i = b * 256 + t;
    int v = (i < NN) ? g_deg[i] : 0;
    sm[t] = v;
    __syncthreads();
    for (int o = 1; o < 256; o <<= 1) {
        int u = (t >= o) ? sm[t - o] : 0;
        __syncthreads();
        sm[t] += u;
        __syncthreads();
    }
    int excl = boff + sm[t] - v;
    if (i < NN) g_rowptr[i] = excl;
    if (i == NN - 1) g_rowptr[NN] = excl + v;
}

__global__ void fill_kernel(const int* __restrict__ ei) {
    int e = blockIdx.x * blockDim.x + threadIdx.x;
    if (e < EE) {
        int src = ei[e];
        int dst = ei[EE + e];
        g_csr[g_rowptr[dst] + g_rank[e]] = src;
    }
}

// ---------------- bf16 tensor-core GEMM, fp8 output, fused alpha epilogue ----------------
// 128x64 tile (was 128x128): half the registers/warp, 2x the blocks -> 3+ blocks/SM
// for cross-block latency hiding. Each warp's epilogue covers exactly ONE head.
#define GBM 128
#define GBN 64
#define GBK 32
__global__ __launch_bounds__(256) void gemm_bf16(const float* __restrict__ A,
                                                 const float* __restrict__ B,
                                                 unsigned char* __restrict__ Cmat,
                                                 const float* __restrict__ a_src,
                                                 const float* __restrict__ a_dst,
                                                 int M, int Nc, int K) {
    __shared__ __nv_bfloat16 As[GBM][GBK + 8];   // ldm 40
    __shared__ __nv_bfloat16 Bs[GBK][GBN + 8];   // ldm 72
    __shared__ float stage[8][16 * 20];

    int tid = threadIdx.x;
    int wid = tid >> 5;
    int lane = tid & 31;
    int wm = wid >> 1;      // 0..3 : 32-row group
    int wn = wid & 1;       // 0..1 : 32-col group (one head)
    int bm = blockIdx.y * GBM;
    int bn = blockIdx.x * GBN;

    wmma::fragment<wmma::accumulator, 16, 16, 16, float> acc[2][2];
#pragma unroll
    for (int i = 0; i < 2; i++)
#pragma unroll
        for (int j = 0; j < 2; j++)
            wmma::fill_fragment(acc[i][j], 0.0f);

    int arow = tid >> 1;            // 0..127
    int acol = (tid & 1) * 16;      // 0 or 16
    int brow = tid >> 3;            // 0..31
    int bcol = (tid & 7) * 8;       // 0..56 step 8

    for (int k0 = 0; k0 < K; k0 += GBK) {
        // A tile: 128x32 fp32 -> bf16
        {
            float4 v[4];
            if (bm + arow < M) {
                const float4* ap = (const float4*)(A + (size_t)(bm + arow) * K + k0 + acol);
#pragma unroll
                for (int t = 0; t < 4; t++) v[t] = ap[t];
            } else {
#pragma unroll
                for (int t = 0; t < 4; t++) v[t] = make_float4(0.f, 0.f, 0.f, 0.f);
            }
            __nv_bfloat16* dstp = &As[arow][acol];
#pragma unroll
            for (int t = 0; t < 4; t++) {
                dstp[4 * t + 0] = __float2bfloat16_rn(v[t].x);
                dstp[4 * t + 1] = __float2bfloat16_rn(v[t].y);
                dstp[4 * t + 2] = __float2bfloat16_rn(v[t].z);
                dstp[4 * t + 3] = __float2bfloat16_rn(v[t].w);
            }
        }
        // B tile: 32x64 fp32 -> bf16 (2 float4 per thread)
        {
            const float4* bp = (const float4*)(B + (size_t)(k0 + brow) * Nc + bn + bcol);
            __nv_bfloat16* dstp = &Bs[brow][bcol];
#pragma unroll
            for (int t = 0; t < 2; t++) {
                float4 v = bp[t];
                dstp[4 * t + 0] = __float2bfloat16_rn(v.x);
                dstp[4 * t + 1] = __float2bfloat16_rn(v.y);
                dstp[4 * t + 2] = __float2bfloat16_rn(v.z);
                dstp[4 * t + 3] = __float2bfloat16_rn(v.w);
            }
        }
        __syncthreads();
#pragma unroll
        for (int ks = 0; ks < GBK; ks += 16) {
            wmma::fragment<wmma::matrix_a, 16, 16, 16, __nv_bfloat16, wmma::row_major> af[2];
#pragma unroll
            for (int i = 0; i < 2; i++)
                wmma::load_matrix_sync(af[i], &As[wm * 32 + i * 16][ks], GBK + 8);
            wmma::fragment<wmma::matrix_b, 16, 16, 16, __nv_bfloat16, wmma::row_major> bf[2];
#pragma unroll
            for (int j = 0; j < 2; j++)
                wmma::load_matrix_sync(bf[j], &Bs[ks][wn * 32 + j * 16], GBN + 8);
#pragma unroll
            for (int i = 0; i < 2; i++)
#pragma unroll
                for (int j = 0; j < 2; j++)
                    wmma::mma_sync(acc[i][j], af[i], bf[j], acc[i][j]);
        }
        __syncthreads();
    }

    // epilogue: fp8 store + fused alpha (one head per warp)
    float* st = &stage[wid][0];
    int lr = lane >> 1;
    int lc = (lane & 1) * 8;
    int head = (bn >> 5) + wn;      // global head index for this warp
#pragma unroll
    for (int i = 0; i < 2; i++) {
        float al_s = 0.f, al_d = 0.f;
        int row = bm + wm * 32 + i * 16 + lr;
#pragma unroll
        for (int j = 0; j < 2; j++) {
            wmma::store_matrix_sync(st, acc[i][j], 20, wmma::mem_row_major);
            __syncwarp();
            if (row < M) {
                int colbase = j * 16 + lc;   // column within head (0..31)
                const float* asp = a_src + head * CC + colbase;
                const float* adp = a_dst + head * CC + colbase;
                unsigned char tmp[8];
#pragma unroll
                for (int t = 0; t < 8; t++) {
                    float v = st[lr * 20 + lc + t];
                    tmp[t] = __nv_cvt_float_to_fp8(v, __NV_SATFINITE, __NV_E4M3);
                    al_s += v * __ldg(asp + t);
                    al_d += v * __ldg(adp + t);
                }
                int col = bn + wn * 32 + j * 16 + lc;
                *(uint2*)(Cmat + (size_t)row * Nc + col) = *(uint2*)tmp;
            }
            __syncwarp();
        }
        float vs = al_s + __shfl_xor_sync(0xffffffffu, al_s, 1);
        float vd = al_d + __shfl_xor_sync(0xffffffffu, al_d, 1);
        if (row < M && (lane & 1) == 0) {
            g_asrc[row * HH + head] = vs;
            g_adst[row * HH + head] = vd;
        }
    }
}

__device__ __forceinline__ float lrelu(float e) { return e > 0.f ? e : NEG_SLOPE * e; }

// fp8x8 (uint2) -> accumulate 8 channels
__device__ __forceinline__ void accum8(float* acc, float ex, const uint2& raw) {
    const unsigned short* p = (const unsigned short*)&raw;
#pragma unroll
    for (int t = 0; t < 4; t++) {
        float2 v = fp8x2_to_float2(p[t]);
        acc[2 * t]     += ex * v.x;
        acc[2 * t + 1] += ex * v.y;
    }
}

// ---------------- single-pass gather aggregation (proven), dual-mode tail ----------------
__global__ __launch_bounds__(256) void aggregate_kernel(const unsigned char* __restrict__ hbuf,
                                                        const float* __restrict__ asrc,
                                                        const float* __restrict__ adst,
                                                        const float* __restrict__ bias,
                                                        float* __restrict__ outbuf,
                                                        const float* __restrict__ Wo,
                                                        const float* __restrict__ bo,
                                                        float* __restrict__ fout) {
    __shared__ float sx[8][32];

    int w = (blockIdx.x * blockDim.x + threadIdx.x) >> 5;
    int wib = threadIdx.x >> 5;
    int lane = threadIdx.x & 31;
    if (w >= NN) return;
    int dst = w;
    int beg = g_rowptr[dst], end = g_rowptr[dst + 1];
    int hd = lane >> 2;
    int cb = (lane & 3) * 8;
    float adst_h = adst[dst * HH + hd];

    float ex_self = __expf(lrelu(asrc[dst * HH + hd] + adst_h));
    float s = ex_self;
    float acc[8] = {0.f, 0.f, 0.f, 0.f, 0.f, 0.f, 0.f, 0.f};
    {
        uint2 raw = *(const uint2*)(hbuf + (size_t)dst * HC + hd * CC + cb);
        accum8(acc, ex_self, raw);
    }

    if (beg < end) {
        int src0 = g_csr[beg];
        float a0 = asrc[src0 * HH + hd];
        uint2 r0 = *(const uint2*)(hbuf + (size_t)src0 * HC + hd * CC + cb);
        for (int i = beg + 1; i < end; ++i) {
            int src1 = g_csr[i];
            float a1 = asrc[src1 * HH + hd];
            uint2 r1 = *(const uint2*)(hbuf + (size_t)src1 * HC + hd * CC + cb);
            float ex = __expf(lrelu(a0 + adst_h));
            s += ex;
            accum8(acc, ex, r0);
            a0 = a1; r0 = r1;
        }
        float ex = __expf(lrelu(a0 + adst_h));
        s += ex;
        accum8(acc, ex, r0);
    }

    float inv = 1.f / s;
#pragma unroll
    for (int j = 0; j < 8; j++) acc[j] *= inv;

#pragma unroll
    for (int j = 0; j < 8; j++) {
        float v = acc[j];
        v += __shfl_xor_sync(0xffffffffu, v, 4);
        v += __shfl_xor_sync(0xffffffffu, v, 8);
        v += __shfl_xor_sync(0xffffffffu, v, 16);
        acc[j] = v * 0.125f;
    }

    if (fout == nullptr) {
        if (lane < 4) {
            float o[8];
#pragma unroll
            for (int j = 0; j < 8; j++) {
                float v = acc[j] + bias[cb + j];
                o[j] = v > 0.f ? v : (__expf(v) - 1.f);
            }
            float4* op = (float4*)(outbuf + (size_t)dst * CC + cb);
            op[0] = make_float4(o[0], o[1], o[2], o[3]);
            op[1] = make_float4(o[4], o[5], o[6], o[7]);
        }
    } else {
        if (lane < 4) {
#pragma unroll
            for (int j = 0; j < 8; j++) {
                float v = acc[j] + bias[cb + j];
                sx[wib][cb + j] = v > 0.f ? v : (__expf(v) - 1.f);
            }
        }
        __syncwarp();
        const float* xv = sx[wib];
        float lg1 = __ldg(bo + lane);
        bool has2 = lane < (NOUT - 32);
        float lg2 = has2 ? __ldg(bo + 32 + lane) : 0.f;
#pragma unroll
        for (int c = 0; c < CC; c++) {
            float xc = xv[c];
            lg1 += xc * __ldg(Wo + c * NOUT + lane);
            if (has2) lg2 += xc * __ldg(Wo + c * NOUT + 32 + lane);
        }
        float m = has2 ? fmaxf(lg1, lg2) : lg1;
#pragma unroll
        for (int o = 16; o > 0; o >>= 1) m = fmaxf(m, __shfl_xor_sync(0xffffffffu, m, o));
        float se = __expf(lg1 - m) + (has2 ? __expf(lg2 - m) : 0.f);
#pragma unroll
        for (int o = 16; o > 0; o >>= 1) se += __shfl_xor_sync(0xffffffffu, se, o);
        float lse = m + __logf(se);
        fout[(size_t)dst * NOUT + lane] = lg1 - lse;
        if (has2) fout[(size_t)dst * NOUT + 32 + lane] = lg2 - lse;
    }
}

// ---------------- launch ----------------
extern "C" void kernel_launch(void* const* d_in, const int* in_sizes, int n_in,
                              void* d_out, int out_size) {
    const float* x   = (const float*)d_in[0];
    const int*   ei  = (const int*)d_in[1];
    const float* W1  = (const float*)d_in[2];
    const float* as1 = (const float*)d_in[3];
    const float* ad1 = (const float*)d_in[4];
    const float* b1  = (const float*)d_in[5];
    const float* W2  = (const float*)d_in[6];
    const float* as2 = (const float*)d_in[7];
    const float* ad2 = (const float*)d_in[8];
    const float* b2  = (const float*)d_in[9];
    const float* Wo  = (const float*)d_in[10];
    const float* bo  = (const float*)d_in[11];
    float* out = (float*)d_out;

    unsigned char* hbuf;
    float *act1, *pasrc, *padst;
    int* pdeg;
    cudaGetSymbolAddress((void**)&hbuf, g_h);
    cudaGetSymbolAddress((void**)&act1, g_act1);
    cudaGetSymbolAddress((void**)&pasrc, g_asrc);
    cudaGetSymbolAddress((void**)&padst, g_adst);
    cudaGetSymbolAddress((void**)&pdeg, g_deg);

    // one-time host resources for the parallel graph branch (no device memory)
    static cudaStream_t s_side = nullptr;
    static cudaEvent_t e_fork = nullptr, e_join = nullptr;
    if (s_side == nullptr) {
        cudaStreamCreateWithFlags(&s_side, cudaStreamNonBlocking);
        cudaEventCreateWithFlags(&e_fork, cudaEventDisableTiming);
        cudaEventCreateWithFlags(&e_join, cudaEventDisableTiming);
    }

    // ---- fork: GEMM1 (w/ fused alpha1) parallel to CSR build ----
    cudaEventRecord(e_fork, 0);
    cudaStreamWaitEvent(s_side, e_fork, 0);

    dim3 gg(HC / GBN, (NN + GBM - 1) / GBM);   // (4, 391)
    gemm_bf16<<<gg, 256, 0, s_side>>>(x, W1, hbuf, as1, ad1, NN, HC, FIN);
    cudaEventRecord(e_join, s_side);

    // ---- CSR build on the main stream (3 kernels + memset) ----
    cudaMemsetAsync(pdeg, 0, NN * sizeof(int), 0);
    count_kernel<<<(EE + 255) / 256, 256>>>(ei);
    scan_kernel<<<NB, 256>>>();
    fill_kernel<<<(EE + 255) / 256, 256>>>(ei);

    // ---- join: aggregate1 needs both branches ----
    cudaStreamWaitEvent(0, e_join, 0);
    aggregate_kernel<<<(NN * 32 + 255) / 256, 256>>>(hbuf, pasrc, padst, b1, act1,
                                                     nullptr, nullptr, nullptr);

    // ---- layer 2: GEMM2 (w/ fused alpha2), then aggregate2 (w/ fused final) ----
    gemm_bf16<<<gg, 256>>>(act1, W2, hbuf, as2, ad2, NN, HC, CC);
    aggregate_kernel<<<(NN * 32 + 255) / 256, 256>>>(hbuf, pasrc, padst, b2, nullptr,
                                                     Wo, bo, out);
}

// round 15
// speedup vs baseline: 1.0360x; 1.0360x over previous
#include <cuda_runtime.h>
#include <cuda_bf16.h>
#include <cuda_fp8.h>
#include <mma.h>

using namespace nvcuda;

#define NN   50000
#define EE   800000
#define FIN  256
#define HH   8
#define CC   32
#define HC   256   // HH*CC
#define NOUT 40
#define NEG_SLOPE 0.2f
#define NB   ((NN + 255) / 256)

// ---------------- device scratch ----------------
__device__ unsigned char g_h[(size_t)NN * HC];   // 12.8 MB : projected features (fp8 e4m3)
__device__ float g_act1[(size_t)NN * CC];
__device__ float g_asrc[NN * HH];
__device__ float g_adst[NN * HH];
__device__ int   g_deg[NN];
__device__ int   g_rowptr[NN + 1];
__device__ int   g_rank[EE];      // per-edge rank within its dst bucket
__device__ int   g_csr[EE];

// fp8x2 -> float2 helper
__device__ __forceinline__ float2 fp8x2_to_float2(unsigned short v) {
    __half2_raw hr = __nv_cvt_fp8x2_to_halfraw2((__nv_fp8x2_storage_t)v, __NV_E4M3);
    return __half22float2(*(__half2*)&hr);
}

// ---------------- CSR build ----------------
__global__ void count_kernel(const int* __restrict__ ei) {
    int e = blockIdx.x * blockDim.x + threadIdx.x;
    if (e < EE) g_rank[e] = atomicAdd(&g_deg[ei[EE + e]], 1);
}

// block b sums deg[0..256b) coalescedly for its offset, then local scan -> rowptr
__global__ void scan_kernel() {
    __shared__ int sm[256];
    __shared__ int swsum[8];
    int b = blockIdx.x, t = threadIdx.x;

    int pre = 0;
    int lim = b * 256;
    for (int base = t; base < lim; base += 256) pre += g_deg[base];
#pragma unroll
    for (int o = 16; o > 0; o >>= 1) pre += __shfl_xor_sync(0xffffffffu, pre, o);
    if ((t & 31) == 0) swsum[t >> 5] = pre;
    __syncthreads();
    int boff = 0;
#pragma unroll
    for (int k = 0; k < 8; k++) boff += swsum[k];

    int i = b * 256 + t;
    int v = (i < NN) ? g_deg[i] : 0;
    sm[t] = v;
    __syncthreads();
    for (int o = 1; o < 256; o <<= 1) {
        int u = (t >= o) ? sm[t - o] : 0;
        __syncthreads();
        sm[t] += u;
        __syncthreads();
    }
    int excl = boff + sm[t] - v;
    if (i < NN) g_rowptr[i] = excl;
    if (i == NN - 1) g_rowptr[NN] = excl + v;
}

__global__ void fill_kernel(const int* __restrict__ ei) {
    int e = blockIdx.x * blockDim.x + threadIdx.x;
    if (e < EE) {
        int src = ei[e];
        int dst = ei[EE + e];
        g_csr[g_rowptr[dst] + g_rank[e]] = src;
    }
}

// ---------------- bf16 tensor-core GEMM, fp8 output, fused alpha epilogue ----------------
// (round-10/13 proven 128x128 version)
#define GBM 128
#define GBN 128
#define GBK 32
__global__ __launch_bounds__(256) void gemm_bf16(const float* __restrict__ A,
                                                 const float* __restrict__ B,
                                                 unsigned char* __restrict__ Cmat,
                                                 const float* __restrict__ a_src,
                                                 const float* __restrict__ a_dst,
                                                 int M, int Nc, int K) {
    __shared__ __nv_bfloat16 As[GBM][GBK + 8];
    __shared__ __nv_bfloat16 Bs[GBK][GBN + 8];
    __shared__ float stage[8][16 * 20];

    int tid = threadIdx.x;
    int wid = tid >> 5;
    int lane = tid & 31;
    int wm = wid >> 1;
    int wn = wid & 1;
    int bm = blockIdx.y * GBM;
    int bn = blockIdx.x * GBN;

    wmma::fragment<wmma::accumulator, 16, 16, 16, float> acc[2][4];
#pragma unroll
    for (int i = 0; i < 2; i++)
#pragma unroll
        for (int j = 0; j < 4; j++)
            wmma::fill_fragment(acc[i][j], 0.0f);

    int arow = tid >> 1;
    int acol = (tid & 1) * 16;
    int brow = tid >> 3;
    int bcol = (tid & 7) * 16;

    for (int k0 = 0; k0 < K; k0 += GBK) {
        {
            float4 v[4];
            if (bm + arow < M) {
                const float4* ap = (const float4*)(A + (size_t)(bm + arow) * K + k0 + acol);
#pragma unroll
                for (int t = 0; t < 4; t++) v[t] = ap[t];
            } else {
#pragma unroll
                for (int t = 0; t < 4; t++) v[t] = make_float4(0.f, 0.f, 0.f, 0.f);
            }
            __nv_bfloat16* dstp = &As[arow][acol];
#pragma unroll
            for (int t = 0; t < 4; t++) {
                dstp[4 * t + 0] = __float2bfloat16_rn(v[t].x);
                dstp[4 * t + 1] = __float2bfloat16_rn(v[t].y);
                dstp[4 * t + 2] = __float2bfloat16_rn(v[t].z);
                dstp[4 * t + 3] = __float2bfloat16_rn(v[t].w);
            }
        }
        {
            const float4* bp = (const float4*)(B + (size_t)(k0 + brow) * Nc + bn + bcol);
            __nv_bfloat16* dstp = &Bs[brow][bcol];
#pragma unroll
            for (int t = 0; t < 4; t++) {
                float4 v = bp[t];
                dstp[4 * t + 0] = __float2bfloat16_rn(v.x);
                dstp[4 * t + 1] = __float2bfloat16_rn(v.y);
                dstp[4 * t + 2] = __float2bfloat16_rn(v.z);
                dstp[4 * t + 3] = __float2bfloat16_rn(v.w);
            }
        }
        __syncthreads();
#pragma unroll
        for (int ks = 0; ks < GBK; ks += 16) {
            wmma::fragment<wmma::matrix_a, 16, 16, 16, __nv_bfloat16, wmma::row_major> af[2];
#pragma unroll
            for (int i = 0; i < 2; i++)
                wmma::load_matrix_sync(af[i], &As[wm * 32 + i * 16][ks], GBK + 8);
            wmma::fragment<wmma::matrix_b, 16, 16, 16, __nv_bfloat16, wmma::row_major> bf[4];
#pragma unroll
            for (int j = 0; j < 4; j++)
                wmma::load_matrix_sync(bf[j], &Bs[ks][wn * 64 + j * 16], GBN + 8);
#pragma unroll
            for (int i = 0; i < 2; i++)
#pragma unroll
                for (int j = 0; j < 4; j++)
                    wmma::mma_sync(acc[i][j], af[i], bf[j], acc[i][j]);
        }
        __syncthreads();
    }

    float* st = &stage[wid][0];
    int lr = lane >> 1;
    int lc = (lane & 1) * 8;
    int hb = (bn >> 5) + wn * 2;   // base head index for this warp (2 heads)
#pragma unroll
    for (int i = 0; i < 2; i++) {
        float al_s[2] = {0.f, 0.f};
        float al_d[2] = {0.f, 0.f};
        int row = bm + wm * 32 + i * 16 + lr;
#pragma unroll
        for (int j = 0; j < 4; j++) {
            wmma::store_matrix_sync(st, acc[i][j], 20, wmma::mem_row_major);
            __syncwarp();
            if (row < M) {
                int h = j >> 1;
                int colbase = (j & 1) * 16 + lc;
                const float* asp = a_src + (hb + h) * CC + colbase;
                const float* adp = a_dst + (hb + h) * CC + colbase;
                unsigned char tmp[8];
#pragma unroll
                for (int t = 0; t < 8; t++) {
                    float v = st[lr * 20 + lc + t];
                    tmp[t] = __nv_cvt_float_to_fp8(v, __NV_SATFINITE, __NV_E4M3);
                    al_s[h] += v * __ldg(asp + t);
                    al_d[h] += v * __ldg(adp + t);
                }
                int col = bn + wn * 64 + j * 16 + lc;
                *(uint2*)(Cmat + (size_t)row * Nc + col) = *(uint2*)tmp;
            }
            __syncwarp();
        }
#pragma unroll
        for (int h = 0; h < 2; h++) {
            float vs = al_s[h] + __shfl_xor_sync(0xffffffffu, al_s[h], 1);
            float vd = al_d[h] + __shfl_xor_sync(0xffffffffu, al_d[h], 1);
            if (row < M && (lane & 1) == 0) {
                g_asrc[row * HH + hb + h] = vs;
                g_adst[row * HH + hb + h] = vd;
            }
        }
    }
}

__device__ __forceinline__ float lrelu(float e) { return e > 0.f ? e : NEG_SLOPE * e; }

// fp8x8 (uint2) -> accumulate 8 channels
__device__ __forceinline__ void accum8(float* acc, float ex, const uint2& raw) {
    const unsigned short* p = (const unsigned short*)&raw;
#pragma unroll
    for (int t = 0; t < 4; t++) {
        float2 v = fp8x2_to_float2(p[t]);
        acc[2 * t]     += ex * v.x;
        acc[2 * t + 1] += ex * v.y;
    }
}

// ---------------- single-pass gather aggregation, dual-mode tail ----------------
// __launch_bounds__(256, 8): cap regs ~32 -> 8 blocks/SM (was 6), +33% warps for
// latency hiding of the per-edge L2 gather chain.
__global__ __launch_bounds__(256, 8) void aggregate_kernel(const unsigned char* __restrict__ hbuf,
                                                           const float* __restrict__ asrc,
                                                           const float* __restrict__ adst,
                                                           const float* __restrict__ bias,
                                                           float* __restrict__ outbuf,
                                                           const float* __restrict__ Wo,
                                                           const float* __restrict__ bo,
                                                           float* __restrict__ fout) {
    __shared__ float sx[8][32];

    int w = (blockIdx.x * blockDim.x + threadIdx.x) >> 5;
    int wib = threadIdx.x >> 5;
    int lane = threadIdx.x & 31;
    if (w >= NN) return;
    int dst = w;
    int beg = g_rowptr[dst], end = g_rowptr[dst + 1];
    int hd = lane >> 2;
    int cb = (lane & 3) * 8;
    float adst_h = adst[dst * HH + hd];

    float ex_self = __expf(lrelu(asrc[dst * HH + hd] + adst_h));
    float s = ex_self;
    float acc[8] = {0.f, 0.f, 0.f, 0.f, 0.f, 0.f, 0.f, 0.f};
    {
        uint2 raw = *(const uint2*)(hbuf + (size_t)dst * HC + hd * CC + cb);
        accum8(acc, ex_self, raw);
    }

    if (beg < end) {
        int src0 = g_csr[beg];
        float a0 = asrc[src0 * HH + hd];
        uint2 r0 = *(const uint2*)(hbuf + (size_t)src0 * HC + hd * CC + cb);
        for (int i = beg + 1; i < end; ++i) {
            int src1 = g_csr[i];
            float a1 = asrc[src1 * HH + hd];
            uint2 r1 = *(const uint2*)(hbuf + (size_t)src1 * HC + hd * CC + cb);
            float ex = __expf(lrelu(a0 + adst_h));
            s += ex;
            accum8(acc, ex, r0);
            a0 = a1; r0 = r1;
        }
        float ex = __expf(lrelu(a0 + adst_h));
        s += ex;
        accum8(acc, ex, r0);
    }

    float inv = 1.f / s;
#pragma unroll
    for (int j = 0; j < 8; j++) acc[j] *= inv;

#pragma unroll
    for (int j = 0; j < 8; j++) {
        float v = acc[j];
        v += __shfl_xor_sync(0xffffffffu, v, 4);
        v += __shfl_xor_sync(0xffffffffu, v, 8);
        v += __shfl_xor_sync(0xffffffffu, v, 16);
        acc[j] = v * 0.125f;
    }

    if (fout == nullptr) {
        if (lane < 4) {
            float o[8];
#pragma unroll
            for (int j = 0; j < 8; j++) {
                float v = acc[j] + bias[cb + j];
                o[j] = v > 0.f ? v : (__expf(v) - 1.f);
            }
            float4* op = (float4*)(outbuf + (size_t)dst * CC + cb);
            op[0] = make_float4(o[0], o[1], o[2], o[3]);
            op[1] = make_float4(o[4], o[5], o[6], o[7]);
        }
    } else {
        if (lane < 4) {
#pragma unroll
            for (int j = 0; j < 8; j++) {
                float v = acc[j] + bias[cb + j];
                sx[wib][cb + j] = v > 0.f ? v : (__expf(v) - 1.f);
            }
        }
        __syncwarp();
        const float* xv = sx[wib];
        float lg1 = __ldg(bo + lane);
        bool has2 = lane < (NOUT - 32);
        float lg2 = has2 ? __ldg(bo + 32 + lane) : 0.f;
#pragma unroll
        for (int c = 0; c < CC; c++) {
            float xc = xv[c];
            lg1 += xc * __ldg(Wo + c * NOUT + lane);
            if (has2) lg2 += xc * __ldg(Wo + c * NOUT + 32 + lane);
        }
        float m = has2 ? fmaxf(lg1, lg2) : lg1;
#pragma unroll
        for (int o = 16; o > 0; o >>= 1) m = fmaxf(m, __shfl_xor_sync(0xffffffffu, m, o));
        float se = __expf(lg1 - m) + (has2 ? __expf(lg2 - m) : 0.f);
#pragma unroll
        for (int o = 16; o > 0; o >>= 1) se += __shfl_xor_sync(0xffffffffu, se, o);
        float lse = m + __logf(se);
        fout[(size_t)dst * NOUT + lane] = lg1 - lse;
        if (has2) fout[(size_t)dst * NOUT + 32 + lane] = lg2 - lse;
    }
}

// ---------------- launch ----------------
extern "C" void kernel_launch(void* const* d_in, const int* in_sizes, int n_in,
                              void* d_out, int out_size) {
    const float* x   = (const float*)d_in[0];
    const int*   ei  = (const int*)d_in[1];
    const float* W1  = (const float*)d_in[2];
    const float* as1 = (const float*)d_in[3];
    const float* ad1 = (const float*)d_in[4];
    const float* b1  = (const float*)d_in[5];
    const float* W2  = (const float*)d_in[6];
    const float* as2 = (const float*)d_in[7];
    const float* ad2 = (const float*)d_in[8];
    const float* b2  = (const float*)d_in[9];
    const float* Wo  = (const float*)d_in[10];
    const float* bo  = (const float*)d_in[11];
    float* out = (float*)d_out;

    unsigned char* hbuf;
    float *act1, *pasrc, *padst;
    int* pdeg;
    cudaGetSymbolAddress((void**)&hbuf, g_h);
    cudaGetSymbolAddress((void**)&act1, g_act1);
    cudaGetSymbolAddress((void**)&pasrc, g_asrc);
    cudaGetSymbolAddress((void**)&padst, g_adst);
    cudaGetSymbolAddress((void**)&pdeg, g_deg);

    // one-time host resources for the parallel graph branch (no device memory)
    static cudaStream_t s_side = nullptr;
    static cudaEvent_t e_fork = nullptr, e_join = nullptr;
    if (s_side == nullptr) {
        cudaStreamCreateWithFlags(&s_side, cudaStreamNonBlocking);
        cudaEventCreateWithFlags(&e_fork, cudaEventDisableTiming);
        cudaEventCreateWithFlags(&e_join, cudaEventDisableTiming);
    }

    // ---- fork: GEMM1 (w/ fused alpha1) parallel to CSR build ----
    cudaEventRecord(e_fork, 0);
    cudaStreamWaitEvent(s_side, e_fork, 0);

    dim3 gg(HC / GBN, (NN + GBM - 1) / GBM);
    gemm_bf16<<<gg, 256, 0, s_side>>>(x, W1, hbuf, as1, ad1, NN, HC, FIN);
    cudaEventRecord(e_join, s_side);

    // ---- CSR build on the main stream (3 kernels + memset) ----
    cudaMemsetAsync(pdeg, 0, NN * sizeof(int), 0);
    count_kernel<<<(EE + 255) / 256, 256>>>(ei);
    scan_kernel<<<NB, 256>>>();
    fill_kernel<<<(EE + 255) / 256, 256>>>(ei);

    // ---- join: aggregate1 needs both branches ----
    cudaStreamWaitEvent(0, e_join, 0);
    aggregate_kernel<<<(NN * 32 + 255) / 256, 256>>>(hbuf, pasrc, padst, b1, act1,
                                                     nullptr, nullptr, nullptr);

    // ---- layer 2: GEMM2 (w/ fused alpha2), then aggregate2 (w/ fused final) ----
    gemm_bf16<<<gg, 256>>>(act1, W2, hbuf, as2, ad2, NN, HC, CC);
    aggregate_kernel<<<(NN * 32 + 255) / 256, 256>>>(hbuf, pasrc, padst, b2, nullptr,
                                                     Wo, bo, out);
}